// round 15
// baseline (speedup 1.0000x reference)
#include <cuda_runtime.h>
#include <cuda_fp16.h>
#include <cstring>

// PositionalSparseLinear: out[b,o] = sum_k x[b, conn[o,k]] * w[o,k]
//   x: [1024,8192] f32   conn: [8192,32] i32   w: [8192,32] f32   out: [1024,8192] f32
//
// Round 15 (R12 base + sound two-choices bank balancing):
//  - fp16-staged transposed SMEM batch tile (BT=8 per 16B col) [R4]
//  - NEW copy B (64KB): columns with (c&8)==0 also stored at
//      8192 + (c>>4)*8 + ((c ^ (c>>4)) & 7)
//    -> alternate bank group gB = (c&7)^((c>>4)&7), independent of gA,
//    collision-free. Prep does SEQUENTIAL greedy two-choices (uint64-packed
//    counters, shfl broadcast) -> near-balanced group histograms
//    (surplus ~6 -> ~2 of 32), then the R11 slot-target schedule.
//    Expected crossbar phases/LDS.128: 4.8 -> ~4.2 (floor 4), and phases
//    cost ~2.07 cyc each on the replay path (the measured binding pipe).
//  - flat chunk split over 148 CTAs, 512 thr x 2 outputs, FFMA2 [R10/R12]

#define IN_F   8192
#define OUT_F  8192
#define KW     32
#define BATCH  1024
#define BT     8
#define THREADS 512
#define N_CTAS 148
#define TOTAL_CHUNKS ((BATCH / BT) * 8)                  // 1024
#define SMEM_U4   (IN_F + IN_F / 2)                      // 12288 uint4
#define SMEM_BYTES (SMEM_U4 * 16)                        // 196608 = 192KB

__device__ unsigned int g_cwT[KW * OUT_F];   // [slot][o] packed (idx<<16)|half(w)

static __device__ __forceinline__ __half2 u32_as_h2(unsigned int u) {
    __half2 h; memcpy(&h, &u, sizeof(h)); return h;
}

// One warp per output o; lane = k.
// 1) two-choices group assignment (sequential greedy, replicated counters)
// 2) R11 slot targeting: slot block for group g: [4*((g-o)&7), +4);
//    rank<4 claims its block, surplus fills deficit slots by ordered match.
__global__ void psl_prep(const int* __restrict__ conn, const float* __restrict__ w)
{
    const int gtid = blockIdx.x * blockDim.x + threadIdx.x;
    const int o    = gtid >> 5;
    const int lane = gtid & 31;

    const int   c  = conn[(size_t)o * KW + lane];
    const float wv = w   [(size_t)o * KW + lane];
    const unsigned short hb = __half_as_ushort(__float2half_rn(wv));

    const int gA   = c & 7;
    const int gB   = (c ^ (c >> 4)) & 7;                  // independent bits
    const int hasB = ((c & 8) == 0) ? 1 : 0;
    const int idxB = 8192 + ((c >> 4) << 3) + gB;         // collision-free

    // ---- sequential greedy two-choices (all lanes replicate counters) ----
    unsigned long long cnt64 = 0ull;                      // 8 counters x 8 bits
    int g = gA, idx = c;
    #pragma unroll 1
    for (int i = 0; i < 32; i++) {
        const int gAi = __shfl_sync(0xffffffffu, gA, i);
        const int gBi = __shfl_sync(0xffffffffu, gB, i);
        const int hBi = __shfl_sync(0xffffffffu, hasB, i);
        const int cA = (int)((cnt64 >> (8 * gAi)) & 0xffull);
        const int cB = (int)((cnt64 >> (8 * gBi)) & 0xffull);
        const int useB = (hBi && (cB < cA)) ? 1 : 0;
        const int gi = useB ? gBi : gAi;
        if (lane == i && useB) { g = gB; idx = idxB; }
        cnt64 += 1ull << (8 * gi);
    }

    const unsigned int packed = ((unsigned int)idx << 16) | (unsigned int)hb;
    const unsigned int lt = (1u << lane) - 1u;

    // ---- rank within final group + R11 slot targeting ----
    int cnt[8];
    int r = 0;
    #pragma unroll
    for (int gg = 0; gg < 8; gg++) {
        unsigned int m = __ballot_sync(0xffffffffu, g == gg);
        cnt[gg] = __popc(m);
        if (gg == g) r = __popc(m & lt);
    }

    int slot;
    unsigned int lm = __ballot_sync(0xffffffffu, r >= 4);
    if (r < 4) {
        slot = 4 * ((g - o) & 7) + r;
    } else {
        int i = __popc(lm & lt);
        int cum = 0, slotg = 0, j = 0;
        #pragma unroll
        for (int gg = 0; gg < 8; gg++) {
            int def = cnt[gg] < 4 ? 4 - cnt[gg] : 0;
            if (i >= cum && i < cum + def) { slotg = gg; j = cnt[gg] + (i - cum); }
            cum += def;
        }
        slot = 4 * ((slotg - o) & 7) + j;
    }

    g_cwT[(size_t)slot * OUT_F + o] = packed;
}

__global__ __launch_bounds__(THREADS, 1)
void psl_main(const float* __restrict__ x, float* __restrict__ out)
{
    extern __shared__ uint4 xs[];   // [0,8192): copy A; [8192,12288): copy B

    const int tid = threadIdx.x;
    const int bid = blockIdx.x;

    const int c_start = (bid * TOTAL_CHUNKS) / N_CTAS;
    const int c_end   = ((bid + 1) * TOTAL_CHUNKS) / N_CTAS;

    int cur_bt = -1;

    #pragma unroll 1
    for (int ch = c_start; ch < c_end; ch++) {
        const int bt = ch >> 3;            // b-tile index
        const int oc = ch & 7;             // output chunk within tile

        if (bt != cur_bt) {
            if (cur_bt >= 0) __syncthreads();   // drain readers of old tile
            const float* xb = x + (size_t)bt * BT * IN_F;
            #pragma unroll
            for (int cc = tid; cc < IN_F; cc += THREADS) {
                float r0 = xb[cc + 0 * (size_t)IN_F];
                float r1 = xb[cc + 1 * (size_t)IN_F];
                float r2 = xb[cc + 2 * (size_t)IN_F];
                float r3 = xb[cc + 3 * (size_t)IN_F];
                float r4 = xb[cc + 4 * (size_t)IN_F];
                float r5 = xb[cc + 5 * (size_t)IN_F];
                float r6 = xb[cc + 6 * (size_t)IN_F];
                float r7 = xb[cc + 7 * (size_t)IN_F];

                __half2 h0 = __floats2half2_rn(r0, r1);
                __half2 h1 = __floats2half2_rn(r2, r3);
                __half2 h2 = __floats2half2_rn(r4, r5);
                __half2 h3 = __floats2half2_rn(r6, r7);

                uint4 v;
                memcpy(&v.x, &h0, 4);
                memcpy(&v.y, &h1, 4);
                memcpy(&v.z, &h2, 4);
                memcpy(&v.w, &h3, 4);
                xs[cc] = v;
                if ((cc & 8) == 0)                      // copy B (half of cols)
                    xs[8192 + ((cc >> 4) << 3) + ((cc ^ (cc >> 4)) & 7)] = v;
            }
            cur_bt = bt;
            __syncthreads();
        }

        // Two outputs per thread: o1 and o1+512. Both preserve o%32==lane.
        const int o1 = oc * 1024 + tid;
        const unsigned int* __restrict__ cwp1 = g_cwT + o1;
        const unsigned int* __restrict__ cwp2 = cwp1 + 512;

        unsigned long long A01 = 0ull, A23 = 0ull, A45 = 0ull, A67 = 0ull;
        unsigned long long B01 = 0ull, B23 = 0ull, B45 = 0ull, B67 = 0ull;

        #pragma unroll 8
        for (int k = 0; k < KW; k++) {
            const unsigned int cw1 = cwp1[(size_t)k * OUT_F];
            const unsigned int cw2 = cwp2[(size_t)k * OUT_F];

            #define PSL_BODY(CW, P01, P23, P45, P67) {                          \
                const int   c_  = (int)((CW) >> 16);                             \
                const float wvf = __half2float(__ushort_as_half(                 \
                                      (unsigned short)((CW) & 0xffffu)));        \
                unsigned long long WV2;                                          \
                asm("mov.b64 %0, {%1, %1};" : "=l"(WV2) : "f"(wvf));             \
                const uint4 hv = xs[c_];                                         \
                float2 f0 = __half22float2(u32_as_h2(hv.x));                     \
                float2 f1 = __half22float2(u32_as_h2(hv.y));                     \
                float2 f2 = __half22float2(u32_as_h2(hv.z));                     \
                float2 f3 = __half22float2(u32_as_h2(hv.w));                     \
                unsigned long long F0, F1, F2, F3;                               \
                asm("mov.b64 %0, {%1, %2};" : "=l"(F0) : "f"(f0.x), "f"(f0.y));  \
                asm("mov.b64 %0, {%1, %2};" : "=l"(F1) : "f"(f1.x), "f"(f1.y));  \
                asm("mov.b64 %0, {%1, %2};" : "=l"(F2) : "f"(f2.x), "f"(f2.y));  \
                asm("mov.b64 %0, {%1, %2};" : "=l"(F3) : "f"(f3.x), "f"(f3.y));  \
                asm("fma.rn.f32x2 %0, %1, %2, %0;" : "+l"(P01) : "l"(F0), "l"(WV2)); \
                asm("fma.rn.f32x2 %0, %1, %2, %0;" : "+l"(P23) : "l"(F1), "l"(WV2)); \
                asm("fma.rn.f32x2 %0, %1, %2, %0;" : "+l"(P45) : "l"(F2), "l"(WV2)); \
                asm("fma.rn.f32x2 %0, %1, %2, %0;" : "+l"(P67) : "l"(F3), "l"(WV2)); \
            }
            PSL_BODY(cw1, A01, A23, A45, A67);
            PSL_BODY(cw2, B01, B23, B45, B67);
            #undef PSL_BODY
        }

        float a0, a1, a2, a3, a4, a5, a6, a7;
        float b0, b1, b2, b3, b4, b5, b6, b7;
        asm("mov.b64 {%0, %1}, %2;" : "=f"(a0), "=f"(a1) : "l"(A01));
        asm("mov.b64 {%0, %1}, %2;" : "=f"(a2), "=f"(a3) : "l"(A23));
        asm("mov.b64 {%0, %1}, %2;" : "=f"(a4), "=f"(a5) : "l"(A45));
        asm("mov.b64 {%0, %1}, %2;" : "=f"(a6), "=f"(a7) : "l"(A67));
        asm("mov.b64 {%0, %1}, %2;" : "=f"(b0), "=f"(b1) : "l"(B01));
        asm("mov.b64 {%0, %1}, %2;" : "=f"(b2), "=f"(b3) : "l"(B23));
        asm("mov.b64 {%0, %1}, %2;" : "=f"(b4), "=f"(b5) : "l"(B45));
        asm("mov.b64 {%0, %1}, %2;" : "=f"(b6), "=f"(b7) : "l"(B67));

        float* op1 = out + (size_t)bt * BT * OUT_F + o1;
        float* op2 = op1 + 512;
        op1[0 * (size_t)OUT_F] = a0;  op2[0 * (size_t)OUT_F] = b0;
        op1[1 * (size_t)OUT_F] = a1;  op2[1 * (size_t)OUT_F] = b1;
        op1[2 * (size_t)OUT_F] = a2;  op2[2 * (size_t)OUT_F] = b2;
        op1[3 * (size_t)OUT_F] = a3;  op2[3 * (size_t)OUT_F] = b3;
        op1[4 * (size_t)OUT_F] = a4;  op2[4 * (size_t)OUT_F] = b4;
        op1[5 * (size_t)OUT_F] = a5;  op2[5 * (size_t)OUT_F] = b5;
        op1[6 * (size_t)OUT_F] = a6;  op2[6 * (size_t)OUT_F] = b6;
        op1[7 * (size_t)OUT_F] = a7;  op2[7 * (size_t)OUT_F] = b7;
    }
}

extern "C" void kernel_launch(void* const* d_in, const int* in_sizes, int n_in,
                              void* d_out, int out_size)
{
    const float* x    = (const float*)d_in[0];   // [1024, 8192] f32
    const int*   conn = (const int*)  d_in[1];   // [8192, 32]   i32
    const float* w    = (const float*)d_in[2];   // [8192, 32]   f32
    float*       out  = (float*)d_out;           // [1024, 8192] f32

    (void)in_sizes; (void)n_in; (void)out_size;

    psl_prep<<<(OUT_F * 32) / 256, 256>>>(conn, w);

    cudaFuncSetAttribute(psl_main,
                         cudaFuncAttributeMaxDynamicSharedMemorySize,
                         SMEM_BYTES);

    psl_main<<<N_CTAS, THREADS, SMEM_BYTES>>>(x, out);   // 148 CTAs, 1 wave
}

// round 16
// speedup vs baseline: 1.0977x; 1.0977x over previous
#include <cuda_runtime.h>
#include <cuda_fp16.h>
#include <cstring>

// PositionalSparseLinear: out[b,o] = sum_k x[b, conn[o,k]] * w[o,k]
//   x: [1024,8192] f32   conn: [8192,32] i32   w: [8192,32] f32   out: [1024,8192] f32
//
// Round 16 (R15 main kernel + ballot-parallel two-choices prep):
//  - fp16-staged transposed SMEM batch tile + independent-hash copy B
//    (columns with (c&8)==0 also at 8192+(c>>4)*8+((c^(c>>4))&7)) [R15]
//  - prep: ONE capacity-limited parallel migration round (ballots only,
//    no serial shfl loop -> prep ~1us instead of ~8us):
//    surplus entries (rank>=4 in gA) move to gB iff cnt[gB]<4, admitted
//    in ballot-rank order up to the deficit -> no overshoot.
//  - then R11 slot targeting; main loop FFMA2, 512 thr x 2 outputs,
//    flat chunk split over 148 CTAs.

#define IN_F   8192
#define OUT_F  8192
#define KW     32
#define BATCH  1024
#define BT     8
#define THREADS 512
#define N_CTAS 148
#define TOTAL_CHUNKS ((BATCH / BT) * 8)                  // 1024
#define SMEM_U4   (IN_F + IN_F / 2)                      // 12288 uint4
#define SMEM_BYTES (SMEM_U4 * 16)                        // 196608 = 192KB

__device__ unsigned int g_cwT[KW * OUT_F];   // [slot][o] packed (idx<<16)|half(w)

static __device__ __forceinline__ __half2 u32_as_h2(unsigned int u) {
    __half2 h; memcpy(&h, &u, sizeof(h)); return h;
}

__global__ void psl_prep(const int* __restrict__ conn, const float* __restrict__ w)
{
    const int gtid = blockIdx.x * blockDim.x + threadIdx.x;
    const int o    = gtid >> 5;
    const int lane = gtid & 31;

    const int   c  = conn[(size_t)o * KW + lane];
    const float wv = w   [(size_t)o * KW + lane];
    const unsigned short hb = __half_as_ushort(__float2half_rn(wv));

    const int gA   = c & 7;
    const int gB   = (c ^ (c >> 4)) & 7;                  // independent hash
    const bool hasB = ((c & 8) == 0) && (gB != gA);
    const int idxB = 8192 + ((c >> 4) << 3) + gB;         // collision-free

    const unsigned int lt = (1u << lane) - 1u;

    // ---- initial counts / rank on gA ----
    int cntA[8]; int rA = 0;
    #pragma unroll
    for (int gg = 0; gg < 8; gg++) {
        unsigned int m = __ballot_sync(0xffffffffu, gA == gg);
        cntA[gg] = __popc(m);
        if (gg == gA) rA = __popc(m & lt);
    }

    // ---- one capacity-limited migration round ----
    // candidate: surplus in gA (rank>=4) with a usable alternate (cnt[gB]<4)
    int cntAgB = 0, capgB = 0;
    #pragma unroll
    for (int gg = 0; gg < 8; gg++) if (gg == gB) cntAgB = cntA[gg];
    capgB = 4 - cntAgB;
    const bool want = hasB && (rA >= 4) && (capgB > 0);

    // admit first cap candidates per target group (ballot-rank order)
    int moveRank = 0;
    #pragma unroll
    for (int gg = 0; gg < 8; gg++) {
        unsigned int m = __ballot_sync(0xffffffffu, want && (gB == gg));
        if (gg == gB) moveRank = __popc(m & lt);
    }
    const bool moved = want && (moveRank < capgB);

    const int g   = moved ? gB : gA;
    const int idx = moved ? idxB : c;
    const unsigned int packed = ((unsigned int)idx << 16) | (unsigned int)hb;

    // ---- final counts / rank + R11 slot targeting ----
    int cnt[8]; int r = 0;
    #pragma unroll
    for (int gg = 0; gg < 8; gg++) {
        unsigned int m = __ballot_sync(0xffffffffu, g == gg);
        cnt[gg] = __popc(m);
        if (gg == g) r = __popc(m & lt);
    }

    int slot;
    unsigned int lm = __ballot_sync(0xffffffffu, r >= 4);
    if (r < 4) {
        slot = 4 * ((g - o) & 7) + r;
    } else {
        int i = __popc(lm & lt);
        int cum = 0, slotg = 0, j = 0;
        #pragma unroll
        for (int gg = 0; gg < 8; gg++) {
            int def = cnt[gg] < 4 ? 4 - cnt[gg] : 0;
            if (i >= cum && i < cum + def) { slotg = gg; j = cnt[gg] + (i - cum); }
            cum += def;
        }
        slot = 4 * ((slotg - o) & 7) + j;
    }

    g_cwT[(size_t)slot * OUT_F + o] = packed;
}

__global__ __launch_bounds__(THREADS, 1)
void psl_main(const float* __restrict__ x, float* __restrict__ out)
{
    extern __shared__ uint4 xs[];   // [0,8192): copy A; [8192,12288): copy B

    const int tid = threadIdx.x;
    const int bid = blockIdx.x;

    const int c_start = (bid * TOTAL_CHUNKS) / N_CTAS;
    const int c_end   = ((bid + 1) * TOTAL_CHUNKS) / N_CTAS;

    int cur_bt = -1;

    #pragma unroll 1
    for (int ch = c_start; ch < c_end; ch++) {
        const int bt = ch >> 3;            // b-tile index
        const int oc = ch & 7;             // output chunk within tile

        if (bt != cur_bt) {
            if (cur_bt >= 0) __syncthreads();   // drain readers of old tile
            const float* xb = x + (size_t)bt * BT * IN_F;
            #pragma unroll
            for (int cc = tid; cc < IN_F; cc += THREADS) {
                float r0 = xb[cc + 0 * (size_t)IN_F];
                float r1 = xb[cc + 1 * (size_t)IN_F];
                float r2 = xb[cc + 2 * (size_t)IN_F];
                float r3 = xb[cc + 3 * (size_t)IN_F];
                float r4 = xb[cc + 4 * (size_t)IN_F];
                float r5 = xb[cc + 5 * (size_t)IN_F];
                float r6 = xb[cc + 6 * (size_t)IN_F];
                float r7 = xb[cc + 7 * (size_t)IN_F];

                __half2 h0 = __floats2half2_rn(r0, r1);
                __half2 h1 = __floats2half2_rn(r2, r3);
                __half2 h2 = __floats2half2_rn(r4, r5);
                __half2 h3 = __floats2half2_rn(r6, r7);

                uint4 v;
                memcpy(&v.x, &h0, 4);
                memcpy(&v.y, &h1, 4);
                memcpy(&v.z, &h2, 4);
                memcpy(&v.w, &h3, 4);
                xs[cc] = v;
                if ((cc & 8) == 0)                      // copy B (half of cols)
                    xs[8192 + ((cc >> 4) << 3) + ((cc ^ (cc >> 4)) & 7)] = v;
            }
            cur_bt = bt;
            __syncthreads();
        }

        // Two outputs per thread: o1 and o1+512. Both preserve o%32==lane.
        const int o1 = oc * 1024 + tid;
        const unsigned int* __restrict__ cwp1 = g_cwT + o1;
        const unsigned int* __restrict__ cwp2 = cwp1 + 512;

        unsigned long long A01 = 0ull, A23 = 0ull, A45 = 0ull, A67 = 0ull;
        unsigned long long B01 = 0ull, B23 = 0ull, B45 = 0ull, B67 = 0ull;

        #pragma unroll 8
        for (int k = 0; k < KW; k++) {
            const unsigned int cw1 = cwp1[(size_t)k * OUT_F];
            const unsigned int cw2 = cwp2[(size_t)k * OUT_F];

            #define PSL_BODY(CW, P01, P23, P45, P67) {                          \
                const int   c_  = (int)((CW) >> 16);                             \
                const float wvf = __half2float(__ushort_as_half(                 \
                                      (unsigned short)((CW) & 0xffffu)));        \
                unsigned long long WV2;                                          \
                asm("mov.b64 %0, {%1, %1};" : "=l"(WV2) : "f"(wvf));             \
                const uint4 hv = xs[c_];                                         \
                float2 f0 = __half22float2(u32_as_h2(hv.x));                     \
                float2 f1 = __half22float2(u32_as_h2(hv.y));                     \
                float2 f2 = __half22float2(u32_as_h2(hv.z));                     \
                float2 f3 = __half22float2(u32_as_h2(hv.w));                     \
                unsigned long long F0, F1, F2, F3;                               \
                asm("mov.b64 %0, {%1, %2};" : "=l"(F0) : "f"(f0.x), "f"(f0.y));  \
                asm("mov.b64 %0, {%1, %2};" : "=l"(F1) : "f"(f1.x), "f"(f1.y));  \
                asm("mov.b64 %0, {%1, %2};" : "=l"(F2) : "f"(f2.x), "f"(f2.y));  \
                asm("mov.b64 %0, {%1, %2};" : "=l"(F3) : "f"(f3.x), "f"(f3.y));  \
                asm("fma.rn.f32x2 %0, %1, %2, %0;" : "+l"(P01) : "l"(F0), "l"(WV2)); \
                asm("fma.rn.f32x2 %0, %1, %2, %0;" : "+l"(P23) : "l"(F1), "l"(WV2)); \
                asm("fma.rn.f32x2 %0, %1, %2, %0;" : "+l"(P45) : "l"(F2), "l"(WV2)); \
                asm("fma.rn.f32x2 %0, %1, %2, %0;" : "+l"(P67) : "l"(F3), "l"(WV2)); \
            }
            PSL_BODY(cw1, A01, A23, A45, A67);
            PSL_BODY(cw2, B01, B23, B45, B67);
            #undef PSL_BODY
        }

        float a0, a1, a2, a3, a4, a5, a6, a7;
        float b0, b1, b2, b3, b4, b5, b6, b7;
        asm("mov.b64 {%0, %1}, %2;" : "=f"(a0), "=f"(a1) : "l"(A01));
        asm("mov.b64 {%0, %1}, %2;" : "=f"(a2), "=f"(a3) : "l"(A23));
        asm("mov.b64 {%0, %1}, %2;" : "=f"(a4), "=f"(a5) : "l"(A45));
        asm("mov.b64 {%0, %1}, %2;" : "=f"(a6), "=f"(a7) : "l"(A67));
        asm("mov.b64 {%0, %1}, %2;" : "=f"(b0), "=f"(b1) : "l"(B01));
        asm("mov.b64 {%0, %1}, %2;" : "=f"(b2), "=f"(b3) : "l"(B23));
        asm("mov.b64 {%0, %1}, %2;" : "=f"(b4), "=f"(b5) : "l"(B45));
        asm("mov.b64 {%0, %1}, %2;" : "=f"(b6), "=f"(b7) : "l"(B67));

        float* op1 = out + (size_t)bt * BT * OUT_F + o1;
        float* op2 = op1 + 512;
        op1[0 * (size_t)OUT_F] = a0;  op2[0 * (size_t)OUT_F] = b0;
        op1[1 * (size_t)OUT_F] = a1;  op2[1 * (size_t)OUT_F] = b1;
        op1[2 * (size_t)OUT_F] = a2;  op2[2 * (size_t)OUT_F] = b2;
        op1[3 * (size_t)OUT_F] = a3;  op2[3 * (size_t)OUT_F] = b3;
        op1[4 * (size_t)OUT_F] = a4;  op2[4 * (size_t)OUT_F] = b4;
        op1[5 * (size_t)OUT_F] = a5;  op2[5 * (size_t)OUT_F] = b5;
        op1[6 * (size_t)OUT_F] = a6;  op2[6 * (size_t)OUT_F] = b6;
        op1[7 * (size_t)OUT_F] = a7;  op2[7 * (size_t)OUT_F] = b7;
    }
}

extern "C" void kernel_launch(void* const* d_in, const int* in_sizes, int n_in,
                              void* d_out, int out_size)
{
    const float* x    = (const float*)d_in[0];   // [1024, 8192] f32
    const int*   conn = (const int*)  d_in[1];   // [8192, 32]   i32
    const float* w    = (const float*)d_in[2];   // [8192, 32]   f32
    float*       out  = (float*)d_out;           // [1024, 8192] f32

    (void)in_sizes; (void)n_in; (void)out_size;

    psl_prep<<<(OUT_F * 32) / 256, 256>>>(conn, w);

    cudaFuncSetAttribute(psl_main,
                         cudaFuncAttributeMaxDynamicSharedMemorySize,
                         SMEM_BYTES);

    psl_main<<<N_CTAS, THREADS, SMEM_BYTES>>>(x, out);   // 148 CTAs, 1 wave
}